// round 1
// baseline (speedup 1.0000x reference)
#include <cuda_runtime.h>

#define NN 50000
#define NE 800000
#define DD 128
#define NL 3
#define NG 256
#define NCLS 10
#define M_TILES 391   // ceil(50000/128)

// ---------------- scratch (static device globals; no allocation) ----------------
__device__ float d_A[NN * DD];          // h (layer output)
__device__ float d_B[NN * DD];          // agg, then z2
__device__ float d_C[NN * DD];          // z1
__device__ float d_sum[DD];
__device__ float d_sumsq[DD];
__device__ float d_scale[DD];
__device__ float d_shift[DD];
__device__ float d_readout[NG * NL * DD];
__device__ int   d_is64;

// ---------------- helpers ----------------
__device__ __forceinline__ unsigned long long pk2(float x, float y) {
    unsigned long long r;
    asm("mov.b64 %0, {%1,%2};" : "=l"(r) : "f"(x), "f"(y));
    return r;
}
__device__ __forceinline__ float2 upk2(unsigned long long v) {
    float2 f;
    asm("mov.b64 {%0,%1}, %2;" : "=f"(f.x), "=f"(f.y) : "l"(v));
    return f;
}
__device__ __forceinline__ void ffma2(unsigned long long& d, unsigned long long a, unsigned long long b) {
    asm("fma.rn.f32x2 %0, %1, %2, %0;" : "+l"(d) : "l"(a), "l"(b));
}
__device__ __forceinline__ void red4(float* p, float4 v) {
    asm volatile("red.global.add.v4.f32 [%0], {%1,%2,%3,%4};"
                 :: "l"(p), "f"(v.x), "f"(v.y), "f"(v.z), "f"(v.w) : "memory");
}

// ---------------- kernels ----------------

// Detect whether edge_index is int64 (odd 32-bit words all zero) or int32.
__global__ void k_detect(const int* __restrict__ ei) {
    if (threadIdx.x == 0 && blockIdx.x == 0) {
        int z = 1;
#pragma unroll
        for (int i = 1; i < 256; i += 2) z &= (ei[i] == 0);
        d_is64 = z;
    }
}

__global__ void k_zero_init() {
    int i = blockIdx.x * 256 + threadIdx.x;
    if (i < NG * NL * DD) d_readout[i] = 0.f;
    if (i < DD) { d_sum[i] = 0.f; d_sumsq[i] = 0.f; }
}

__global__ void k_zero_B() {
    int i = blockIdx.x * 256 + threadIdx.x;   // grid sized exactly NN*DD/4
    ((float4*)d_B)[i] = make_float4(0.f, 0.f, 0.f, 0.f);
}

// One warp per edge: gather h[src] (128 floats = 32 lanes x float4),
// vector-reduce into agg[dst].
__global__ void k_scatter(const float* __restrict__ h, const int* __restrict__ ei) {
    int gt = blockIdx.x * blockDim.x + threadIdx.x;
    int e = gt >> 5;
    if (e >= NE) return;
    int lane = threadIdx.x & 31;
    int src = 0, dst = 0;
    if (lane == 0) {
        if (d_is64) { src = ei[2 * e]; dst = ei[2 * (NE + e)]; }
        else        { src = ei[e];     dst = ei[NE + e]; }
    }
    src = __shfl_sync(0xffffffffu, src, 0);
    dst = __shfl_sync(0xffffffffu, dst, 0);
    float4 v = ((const float4*)(h + src * DD))[lane];
    red4(d_B + dst * DD + lane * 4, v);
}

// C[M,128] = f(A) @ W + bias
// MODE 0: f(A) = P + Q            (GIN input: h + agg)
// MODE 1: f(A) = relu(P*scale+shift)   (BN1 affine + ReLU folded into A-load)
template <int MODE>
__global__ void __launch_bounds__(256, 2)
k_gemm(const float* __restrict__ P, const float* __restrict__ Q,
       const float* __restrict__ W, const float* __restrict__ bias,
       float* __restrict__ out) {
    __shared__ float As[32][132];
    __shared__ float Ws[32][132];
    __shared__ float ssc[DD], ssh[DD];

    int t = threadIdx.x;
    if (MODE == 1 && t < DD) { ssc[t] = d_scale[t]; ssh[t] = d_shift[t]; }

    int tx = t & 15, ty = t >> 4;
    int row0 = blockIdx.x * 128;
    int n0 = tx * 8;

    float4 bb0 = *(const float4*)(bias + n0);
    float4 bb1 = *(const float4*)(bias + n0 + 4);
    unsigned long long ib[4] = { pk2(bb0.x, bb0.y), pk2(bb0.z, bb0.w),
                                 pk2(bb1.x, bb1.y), pk2(bb1.z, bb1.w) };
    unsigned long long acc[8][4];
#pragma unroll
    for (int i = 0; i < 8; i++)
#pragma unroll
        for (int j = 0; j < 4; j++) acc[i][j] = ib[j];

    __syncthreads();  // ssc/ssh visible

    for (int kk = 0; kk < 128; kk += 32) {
        // A tile [128 rows x 32 k], stored transposed As[k][m]
#pragma unroll
        for (int i = 0; i < 4; i++) {
            int id = t + i * 256;
            int row = id >> 3;
            int kc = (id & 7) << 2;
            int gr = row0 + row;
            float4 v = make_float4(0.f, 0.f, 0.f, 0.f);
            if (gr < NN) {
                v = *(const float4*)(P + gr * DD + kk + kc);
                if (MODE == 0) {
                    float4 q = *(const float4*)(Q + gr * DD + kk + kc);
                    v.x += q.x; v.y += q.y; v.z += q.z; v.w += q.w;
                } else {
                    int c = kk + kc;
                    v.x = fmaxf(fmaf(v.x, ssc[c + 0], ssh[c + 0]), 0.f);
                    v.y = fmaxf(fmaf(v.y, ssc[c + 1], ssh[c + 1]), 0.f);
                    v.z = fmaxf(fmaf(v.z, ssc[c + 2], ssh[c + 2]), 0.f);
                    v.w = fmaxf(fmaf(v.w, ssc[c + 3], ssh[c + 3]), 0.f);
                }
            }
            As[kc + 0][row] = v.x;
            As[kc + 1][row] = v.y;
            As[kc + 2][row] = v.z;
            As[kc + 3][row] = v.w;
        }
        // W tile [32 k x 128 n]
#pragma unroll
        for (int i = 0; i < 4; i++) {
            int id = t + i * 256;
            int k = id >> 5;
            int nc = (id & 31) << 2;
            *(float4*)&Ws[k][nc] = *(const float4*)(W + (kk + k) * DD + nc);
        }
        __syncthreads();

#pragma unroll 8
        for (int k = 0; k < 32; k++) {
            float4 a0 = *(float4*)&As[k][ty * 8];
            float4 a1 = *(float4*)&As[k][ty * 8 + 4];
            float4 w0 = *(float4*)&Ws[k][n0];
            float4 w1 = *(float4*)&Ws[k][n0 + 4];
            unsigned long long bp[4] = { pk2(w0.x, w0.y), pk2(w0.z, w0.w),
                                         pk2(w1.x, w1.y), pk2(w1.z, w1.w) };
            unsigned long long ap[8] = { pk2(a0.x, a0.x), pk2(a0.y, a0.y),
                                         pk2(a0.z, a0.z), pk2(a0.w, a0.w),
                                         pk2(a1.x, a1.x), pk2(a1.y, a1.y),
                                         pk2(a1.z, a1.z), pk2(a1.w, a1.w) };
#pragma unroll
            for (int i = 0; i < 8; i++)
#pragma unroll
                for (int j = 0; j < 4; j++) ffma2(acc[i][j], ap[i], bp[j]);
        }
        __syncthreads();
    }

#pragma unroll
    for (int i = 0; i < 8; i++) {
        int gr = row0 + ty * 8 + i;
        if (gr < NN) {
            float2 r0 = upk2(acc[i][0]), r1 = upk2(acc[i][1]);
            float2 r2 = upk2(acc[i][2]), r3 = upk2(acc[i][3]);
            *(float4*)(out + gr * DD + n0)     = make_float4(r0.x, r0.y, r1.x, r1.y);
            *(float4*)(out + gr * DD + n0 + 4) = make_float4(r2.x, r2.y, r3.x, r3.y);
        }
    }
}

// Column sums / sums-of-squares for BN statistics.
__global__ void k_stats(const float* __restrict__ Z) {
    int col = threadIdx.x;                 // 128 threads
    int row0 = blockIdx.x * 128;
    int nr = min(128, NN - row0);
    const float* p = Z + row0 * DD + col;
    float s = 0.f, ss = 0.f;
#pragma unroll 4
    for (int r = 0; r < nr; r++) {
        float v = p[r * DD];
        s += v;
        ss = fmaf(v, v, ss);
    }
    atomicAdd(&d_sum[col], s);
    atomicAdd(&d_sumsq[col], ss);
}

__global__ void k_finalize(const float* __restrict__ g, const float* __restrict__ bt) {
    int c = threadIdx.x;
    float mu = d_sum[c] * (1.f / NN);
    float var = d_sumsq[c] * (1.f / NN) - mu * mu;
    float r = rsqrtf(var + 1e-5f);
    float sc = g[c] * r;
    d_scale[c] = sc;
    d_shift[c] = fmaf(-mu, sc, bt[c]);
    d_sum[c] = 0.f;
    d_sumsq[c] = 0.f;
}

// Final BN+ReLU of the layer, write h, and vector-reduce into readout[batch].
__global__ void k_epilogue(const float* __restrict__ Z, const int* __restrict__ batch, int layer) {
    int i = blockIdx.x * 256 + threadIdx.x;   // grid sized exactly NN*32
    int node = i >> 5;
    int c4 = (i & 31) << 2;
    float4 z = *(const float4*)(Z + node * DD + c4);
    z.x = fmaxf(fmaf(z.x, d_scale[c4 + 0], d_shift[c4 + 0]), 0.f);
    z.y = fmaxf(fmaf(z.y, d_scale[c4 + 1], d_shift[c4 + 1]), 0.f);
    z.z = fmaxf(fmaf(z.z, d_scale[c4 + 2], d_shift[c4 + 2]), 0.f);
    z.w = fmaxf(fmaf(z.w, d_scale[c4 + 3], d_shift[c4 + 3]), 0.f);
    *(float4*)(d_A + node * DD + c4) = z;
    int b = d_is64 ? batch[2 * node] : batch[node];
    red4(d_readout + b * (NL * DD) + layer * DD + c4, z);
}

// out[g,:] = relu(readout[g,:] @ Wc1 + bc1) @ Wc2 + bc2
__global__ void k_classifier(const float* __restrict__ Wc1, const float* __restrict__ bc1,
                             const float* __restrict__ Wc2, const float* __restrict__ bc2,
                             float* __restrict__ out) {
    int g = blockIdx.x;
    int t = threadIdx.x;                    // 128 threads
    __shared__ float red[NCLS];
    const float* r = d_readout + g * (NL * DD);
    float acc = bc1[t];
#pragma unroll 4
    for (int k = 0; k < NL * DD; k++) acc = fmaf(r[k], Wc1[k * DD + t], acc);
    float h = fmaxf(acc, 0.f);
    if (t < NCLS) red[t] = 0.f;
    __syncthreads();
#pragma unroll
    for (int c = 0; c < NCLS; c++) atomicAdd(&red[c], h * Wc2[t * NCLS + c]);
    __syncthreads();
    if (t < NCLS) out[g * NCLS + t] = red[t] + bc2[t];
}

// ---------------- launcher ----------------
extern "C" void kernel_launch(void* const* d_in, const int* in_sizes, int n_in,
                              void* d_out, int out_size) {
    const float* x   = (const float*)d_in[0];
    const int*   ei  = (const int*)d_in[1];
    const int*   bat = (const int*)d_in[2];
    const float* W1  = (const float*)d_in[3];
    const float* b1  = (const float*)d_in[4];
    const float* g1  = (const float*)d_in[5];
    const float* bt1 = (const float*)d_in[6];
    const float* W2  = (const float*)d_in[7];
    const float* b2  = (const float*)d_in[8];
    const float* g2  = (const float*)d_in[9];
    const float* bt2 = (const float*)d_in[10];
    const float* Wc1 = (const float*)d_in[11];
    const float* bc1 = (const float*)d_in[12];
    const float* Wc2 = (const float*)d_in[13];
    const float* bc2 = (const float*)d_in[14];
    float* out = (float*)d_out;

    float *pA, *pB, *pC;
    cudaGetSymbolAddress((void**)&pA, d_A);
    cudaGetSymbolAddress((void**)&pB, d_B);
    cudaGetSymbolAddress((void**)&pC, d_C);

    k_detect<<<1, 32>>>(ei);
    k_zero_init<<<384, 256>>>();

    for (int L = 0; L < NL; L++) {
        const float* h = (L == 0) ? x : pA;
        k_zero_B<<<(NN * DD / 4) / 256, 256>>>();
        k_scatter<<<(NE * 32) / 256, 256>>>(h, ei);
        k_gemm<0><<<M_TILES, 256>>>(h, pB, W1 + L * DD * DD, b1 + L * DD, pC);
        k_stats<<<M_TILES, 128>>>(pC);
        k_finalize<<<1, 128>>>(g1 + L * DD, bt1 + L * DD);
        k_gemm<1><<<M_TILES, 256>>>(pC, nullptr, W2 + L * DD * DD, b2 + L * DD, pB);
        k_stats<<<M_TILES, 128>>>(pB);
        k_finalize<<<1, 128>>>(g2 + L * DD, bt2 + L * DD);
        k_epilogue<<<(NN * 32) / 256, 256>>>(pB, bat, L);
    }
    k_classifier<<<NG, 128>>>(Wc1, bc1, Wc2, bc2, out);
}

// round 2
// speedup vs baseline: 1.5493x; 1.5493x over previous
#include <cuda_runtime.h>

#define NN 50000
#define NE 800000
#define DD 128
#define NL 3
#define NG 256
#define NCLS 10
#define M_TILES 391   // ceil(50000/128)

// ---------------- scratch (static device globals; no allocation) ----------------
__device__ float d_A[NN * DD];          // h (layer output)
__device__ float d_B[NN * DD];          // agg (h+sum), then z2
__device__ float d_C[NN * DD];          // z1
__device__ float d_stats[NL * 2 * 2 * DD];   // per (layer, bn#): [sum[128] | sumsq[128]]
__device__ float d_readout[NG * NL * DD];
__device__ int   d_deg[NN];
__device__ int   d_cur[NN];
__device__ int   d_off[NN + 1];
__device__ int   d_csr[NE];
__device__ int   d_bsum[256];
__device__ int   d_is64;

// ---------------- helpers ----------------
__device__ __forceinline__ unsigned long long pk2(float x, float y) {
    unsigned long long r;
    asm("mov.b64 %0, {%1,%2};" : "=l"(r) : "f"(x), "f"(y));
    return r;
}
__device__ __forceinline__ float2 upk2(unsigned long long v) {
    float2 f;
    asm("mov.b64 {%0,%1}, %2;" : "=f"(f.x), "=f"(f.y) : "l"(v));
    return f;
}
__device__ __forceinline__ void ffma2(unsigned long long& d, unsigned long long a, unsigned long long b) {
    asm("fma.rn.f32x2 %0, %1, %2, %0;" : "+l"(d) : "l"(a), "l"(b));
}
__device__ __forceinline__ void red4(float* p, float4 v) {
    asm volatile("red.global.add.v4.f32 [%0], {%1,%2,%3,%4};"
                 :: "l"(p), "f"(v.x), "f"(v.y), "f"(v.z), "f"(v.w) : "memory");
}
__device__ __forceinline__ unsigned smem_u32(const void* p) {
    unsigned r;
    asm("{ .reg .u64 t; cvta.to.shared.u64 t, %1; cvt.u32.u64 %0, t; }" : "=r"(r) : "l"(p));
    return r;
}
__device__ __forceinline__ void cpasync16(unsigned dst, const void* src) {
    asm volatile("cp.async.cg.shared.global [%0], [%1], 16;" :: "r"(dst), "l"(src));
}

// ---------------- small kernels ----------------

// Detect whether edge_index is int64 (odd 32-bit words all zero) or int32.
__global__ void k_detect(const int* __restrict__ ei) {
    if (threadIdx.x == 0 && blockIdx.x == 0) {
        int z = 1;
#pragma unroll
        for (int i = 1; i < 256; i += 2) z &= (ei[i] == 0);
        d_is64 = z;
    }
}

__global__ void k_zero_init() {
    int i = blockIdx.x * 256 + threadIdx.x;   // 384*256 = 98304 threads
    if (i < NG * NL * DD) d_readout[i] = 0.f;
    if (i < NL * 2 * 2 * DD) d_stats[i] = 0.f;
    if (i < NN) d_deg[i] = 0;
}

__global__ void k_hist(const int* __restrict__ ei) {
    int e = blockIdx.x * 256 + threadIdx.x;
    if (e >= NE) return;
    int dst = d_is64 ? ei[2 * (NE + e)] : ei[NE + e];
    atomicAdd(&d_deg[dst], 1);
}

__global__ void k_scan1() {
    __shared__ int s[256];
    int t = threadIdx.x;
    int i = blockIdx.x * 256 + t;
    int v = (i < NN) ? d_deg[i] : 0;
    s[t] = v;
    __syncthreads();
#pragma unroll
    for (int d = 1; d < 256; d <<= 1) {
        int x = (t >= d) ? s[t - d] : 0;
        __syncthreads();
        s[t] += x;
        __syncthreads();
    }
    if (i < NN) d_off[i + 1] = s[t];
    if (t == 255) d_bsum[blockIdx.x] = s[255];
}

__global__ void k_scan2() {
    __shared__ int s[256];
    int t = threadIdx.x;
    int v = (t < 196) ? d_bsum[t] : 0;
    s[t] = v;
    __syncthreads();
#pragma unroll
    for (int d = 1; d < 256; d <<= 1) {
        int x = (t >= d) ? s[t - d] : 0;
        __syncthreads();
        s[t] += x;
        __syncthreads();
    }
    if (t < 196) d_bsum[t] = s[t] - v;   // exclusive prefix
}

__global__ void k_scan3() {
    int i = blockIdx.x * 256 + threadIdx.x;
    if (i < NN) { d_off[i + 1] += d_bsum[blockIdx.x]; d_cur[i] = 0; }
    if (i == 0) d_off[0] = 0;
}

__global__ void k_fill(const int* __restrict__ ei) {
    int e = blockIdx.x * 256 + threadIdx.x;
    if (e >= NE) return;
    int src, dst;
    if (d_is64) { src = ei[2 * e]; dst = ei[2 * (NE + e)]; }
    else        { src = ei[e];     dst = ei[NE + e]; }
    int p = atomicAdd(&d_cur[dst], 1);
    d_csr[d_off[dst] + p] = src;
}

// One warp per node: agg = h[node] + sum_{src in CSR[node]} h[src], written once.
__global__ void k_agg(const float* __restrict__ h) {
    int w = (blockIdx.x * 256 + threadIdx.x) >> 5;
    if (w >= NN) return;
    int lane = threadIdx.x & 31;
    int beg = d_off[w], end = d_off[w + 1];
    const float4* hv = (const float4*)h;
    float4 a = hv[(long)w * 32 + lane];
    int j = beg;
    for (; j + 4 <= end; j += 4) {
        int s0 = d_csr[j], s1 = d_csr[j + 1], s2 = d_csr[j + 2], s3 = d_csr[j + 3];
        float4 v0 = hv[(long)s0 * 32 + lane];
        float4 v1 = hv[(long)s1 * 32 + lane];
        float4 v2 = hv[(long)s2 * 32 + lane];
        float4 v3 = hv[(long)s3 * 32 + lane];
        a.x += (v0.x + v1.x) + (v2.x + v3.x);
        a.y += (v0.y + v1.y) + (v2.y + v3.y);
        a.z += (v0.z + v1.z) + (v2.z + v3.z);
        a.w += (v0.w + v1.w) + (v2.w + v3.w);
    }
    for (; j < end; j++) {
        int s0 = d_csr[j];
        float4 v = hv[(long)s0 * 32 + lane];
        a.x += v.x; a.y += v.y; a.z += v.z; a.w += v.w;
    }
    ((float4*)d_B)[(long)w * 32 + lane] = a;
}

// ---------------- GEMM: out[M,128] = f(P) @ W + bias, fused BN-stats output ----
// MODE 0: f = identity      (agg already includes self term)
// MODE 1: f = relu(P * scale + shift), scale/shift computed inline from statsIn
template <int MODE>
__global__ void __launch_bounds__(256, 2)
k_gemm(const float* __restrict__ P, const float* __restrict__ W,
       const float* __restrict__ bias,
       const float* __restrict__ g, const float* __restrict__ bt,
       const float* __restrict__ statsIn, float* __restrict__ statsOut,
       float* __restrict__ out) {
    __shared__ float As[32 * 128];       // swizzled: elem (k,m) at k*128 + (m ^ (k&28))
    __shared__ float Ws[2][32 * 128];    // double-buffered via cp.async

    int t = threadIdx.x;
    int tx = t & 15, ty = t >> 4;
    int row0 = blockIdx.x * 128;
    int n0 = tx * 8;
    int kc = (t & 7) << 2;               // constant A-column group per thread
    int ty8 = ty * 8;

    // ---- prologue: W chunk0 via cp.async, A chunk0 via register prefetch ----
    {
        unsigned base = smem_u32(&Ws[0][0]);
#pragma unroll
        for (int i = 0; i < 4; i++) {
            int idx = t + i * 256;
            int k = idx >> 5, nc = (idx & 31) << 2;
            cpasync16(base + (unsigned)(k * 128 + nc) * 4u, W + k * DD + nc);
        }
        asm volatile("cp.async.commit_group;");
    }
    float4 pa[4];
#pragma unroll
    for (int i = 0; i < 4; i++) {
        int row = (t + i * 256) >> 3;
        int gr = row0 + row;
        pa[i] = (gr < NN) ? *(const float4*)(P + (long)gr * DD + kc)
                          : make_float4(0.f, 0.f, 0.f, 0.f);
    }

    float4 bb0 = *(const float4*)(bias + n0);
    float4 bb1 = *(const float4*)(bias + n0 + 4);
    unsigned long long ib[4] = { pk2(bb0.x, bb0.y), pk2(bb0.z, bb0.w),
                                 pk2(bb1.x, bb1.y), pk2(bb1.z, bb1.w) };
    unsigned long long acc[8][4];
#pragma unroll
    for (int i = 0; i < 8; i++)
#pragma unroll
        for (int j = 0; j < 4; j++) acc[i][j] = ib[j];

    // ---- main loop over 4 K-chunks of 32 ----
    for (int c = 0; c < 4; c++) {
        int kk = c * 32;

        float4 sc4, sh4;
        if (MODE == 1) {
            int c0 = kk + kc;
            float4 sm = *(const float4*)(statsIn + c0);
            float4 sq = *(const float4*)(statsIn + DD + c0);
            float4 gv = *(const float4*)(g + c0);
            float4 bv = *(const float4*)(bt + c0);
            float mu, var, r;
            mu = sm.x * (1.f / NN); var = sq.x * (1.f / NN) - mu * mu;
            r = rsqrtf(var + 1e-5f); sc4.x = gv.x * r; sh4.x = fmaf(-mu, sc4.x, bv.x);
            mu = sm.y * (1.f / NN); var = sq.y * (1.f / NN) - mu * mu;
            r = rsqrtf(var + 1e-5f); sc4.y = gv.y * r; sh4.y = fmaf(-mu, sc4.y, bv.y);
            mu = sm.z * (1.f / NN); var = sq.z * (1.f / NN) - mu * mu;
            r = rsqrtf(var + 1e-5f); sc4.z = gv.z * r; sh4.z = fmaf(-mu, sc4.z, bv.z);
            mu = sm.w * (1.f / NN); var = sq.w * (1.f / NN) - mu * mu;
            r = rsqrtf(var + 1e-5f); sc4.w = gv.w * r; sh4.w = fmaf(-mu, sc4.w, bv.w);
        }

        // STS A (with MODE transform), swizzled stores (conflict-free)
#pragma unroll
        for (int i = 0; i < 4; i++) {
            int row = (t + i * 256) >> 3;
            float4 v = pa[i];
            if (MODE == 1) {
                v.x = fmaxf(fmaf(v.x, sc4.x, sh4.x), 0.f);
                v.y = fmaxf(fmaf(v.y, sc4.y, sh4.y), 0.f);
                v.z = fmaxf(fmaf(v.z, sc4.z, sh4.z), 0.f);
                v.w = fmaxf(fmaf(v.w, sc4.w, sh4.w), 0.f);
            }
            int rs = row ^ kc;           // (k & 28) == kc for all 4 columns
            As[(kc + 0) * 128 + rs] = v.x;
            As[(kc + 1) * 128 + rs] = v.y;
            As[(kc + 2) * 128 + rs] = v.z;
            As[(kc + 3) * 128 + rs] = v.w;
        }

        // issue next W chunk, wait current
        if (c < 3) {
            unsigned base = smem_u32(&Ws[(c + 1) & 1][0]);
#pragma unroll
            for (int i = 0; i < 4; i++) {
                int idx = t + i * 256;
                int k = idx >> 5, nc = (idx & 31) << 2;
                cpasync16(base + (unsigned)(k * 128 + nc) * 4u, W + (kk + 32 + k) * DD + nc);
            }
            asm volatile("cp.async.commit_group;");
            asm volatile("cp.async.wait_group 1;");
        } else {
            asm volatile("cp.async.wait_group 0;");
        }
        __syncthreads();

        // prefetch next A chunk (overlaps compute below)
        if (c < 3) {
#pragma unroll
            for (int i = 0; i < 4; i++) {
                int row = (t + i * 256) >> 3;
                int gr = row0 + row;
                pa[i] = (gr < NN) ? *(const float4*)(P + (long)gr * DD + kk + 32 + kc)
                                  : make_float4(0.f, 0.f, 0.f, 0.f);
            }
        }

        const float* wb = Ws[c & 1];
#pragma unroll 8
        for (int k = 0; k < 32; k++) {
            int s = k & 28;
            float4 a0 = *(const float4*)&As[k * 128 + (ty8 ^ s)];
            float4 a1 = *(const float4*)&As[k * 128 + ((ty8 + 4) ^ s)];
            float4 w0 = *(const float4*)&wb[k * 128 + n0];
            float4 w1 = *(const float4*)&wb[k * 128 + n0 + 4];
            unsigned long long bp[4] = { pk2(w0.x, w0.y), pk2(w0.z, w0.w),
                                         pk2(w1.x, w1.y), pk2(w1.z, w1.w) };
            unsigned long long ap[8] = { pk2(a0.x, a0.x), pk2(a0.y, a0.y),
                                         pk2(a0.z, a0.z), pk2(a0.w, a0.w),
                                         pk2(a1.x, a1.x), pk2(a1.y, a1.y),
                                         pk2(a1.z, a1.z), pk2(a1.w, a1.w) };
#pragma unroll
            for (int i = 0; i < 8; i++)
#pragma unroll
                for (int j = 0; j < 4; j++) ffma2(acc[i][j], ap[i], bp[j]);
        }
        __syncthreads();
    }

    // ---- epilogue: store output + fused BN column stats ----
    float s8[8] = {0, 0, 0, 0, 0, 0, 0, 0};
    float q8[8] = {0, 0, 0, 0, 0, 0, 0, 0};
#pragma unroll
    for (int i = 0; i < 8; i++) {
        int gr = row0 + ty8 + i;
        if (gr < NN) {
            float2 r0 = upk2(acc[i][0]), r1 = upk2(acc[i][1]);
            float2 r2 = upk2(acc[i][2]), r3 = upk2(acc[i][3]);
            *(float4*)(out + (long)gr * DD + n0)     = make_float4(r0.x, r0.y, r1.x, r1.y);
            *(float4*)(out + (long)gr * DD + n0 + 4) = make_float4(r2.x, r2.y, r3.x, r3.y);
            s8[0] += r0.x; q8[0] = fmaf(r0.x, r0.x, q8[0]);
            s8[1] += r0.y; q8[1] = fmaf(r0.y, r0.y, q8[1]);
            s8[2] += r1.x; q8[2] = fmaf(r1.x, r1.x, q8[2]);
            s8[3] += r1.y; q8[3] = fmaf(r1.y, r1.y, q8[3]);
            s8[4] += r2.x; q8[4] = fmaf(r2.x, r2.x, q8[4]);
            s8[5] += r2.y; q8[5] = fmaf(r2.y, r2.y, q8[5]);
            s8[6] += r3.x; q8[6] = fmaf(r3.x, r3.x, q8[6]);
            s8[7] += r3.y; q8[7] = fmaf(r3.y, r3.y, q8[7]);
        }
    }
    float* Sa = As;            // [16][128]
    float* Sb = As + 2048;     // [16][128]
#pragma unroll
    for (int j = 0; j < 8; j++) {
        Sa[ty * 128 + n0 + j] = s8[j];
        Sb[ty * 128 + n0 + j] = q8[j];
    }
    __syncthreads();
    if (t < 128) {
        float S = 0.f, Q = 0.f;
#pragma unroll
        for (int r = 0; r < 16; r++) { S += Sa[r * 128 + t]; Q += Sb[r * 128 + t]; }
        atomicAdd(&statsOut[t], S);
        atomicAdd(&statsOut[DD + t], Q);
    }
}

// Final BN+ReLU of the layer, write h, and vector-reduce into readout[batch].
__global__ void k_epilogue(const float* __restrict__ Z, const int* __restrict__ batch,
                           const float* __restrict__ g, const float* __restrict__ bt,
                           const float* __restrict__ statsIn, int layer) {
    __shared__ float esc[DD], esh[DD];
    int t = threadIdx.x;
    if (t < DD) {
        float mu = statsIn[t] * (1.f / NN);
        float var = statsIn[DD + t] * (1.f / NN) - mu * mu;
        float r = rsqrtf(var + 1e-5f);
        float sc = g[t] * r;
        esc[t] = sc;
        esh[t] = fmaf(-mu, sc, bt[t]);
    }
    __syncthreads();
    int i = blockIdx.x * 256 + t;          // grid sized exactly NN*32
    int node = i >> 5;
    int c4 = (i & 31) << 2;
    float4 z = *(const float4*)(Z + (long)node * DD + c4);
    z.x = fmaxf(fmaf(z.x, esc[c4 + 0], esh[c4 + 0]), 0.f);
    z.y = fmaxf(fmaf(z.y, esc[c4 + 1], esh[c4 + 1]), 0.f);
    z.z = fmaxf(fmaf(z.z, esc[c4 + 2], esh[c4 + 2]), 0.f);
    z.w = fmaxf(fmaf(z.w, esc[c4 + 3], esh[c4 + 3]), 0.f);
    *(float4*)(d_A + (long)node * DD + c4) = z;
    int b = d_is64 ? batch[2 * node] : batch[node];
    red4(d_readout + b * (NL * DD) + layer * DD + c4, z);
}

// out[g,:] = relu(readout[g,:] @ Wc1 + bc1) @ Wc2 + bc2
__global__ void k_classifier(const float* __restrict__ Wc1, const float* __restrict__ bc1,
                             const float* __restrict__ Wc2, const float* __restrict__ bc2,
                             float* __restrict__ out) {
    int gidx = blockIdx.x;
    int t = threadIdx.x;                    // 128 threads
    __shared__ float red[NCLS];
    const float* r = d_readout + gidx * (NL * DD);
    float acc = bc1[t];
#pragma unroll 4
    for (int k = 0; k < NL * DD; k++) acc = fmaf(r[k], Wc1[k * DD + t], acc);
    float h = fmaxf(acc, 0.f);
    if (t < NCLS) red[t] = 0.f;
    __syncthreads();
#pragma unroll
    for (int c = 0; c < NCLS; c++) atomicAdd(&red[c], h * Wc2[t * NCLS + c]);
    __syncthreads();
    if (t < NCLS) out[gidx * NCLS + t] = red[t] + bc2[t];
}

// ---------------- launcher ----------------
extern "C" void kernel_launch(void* const* d_in, const int* in_sizes, int n_in,
                              void* d_out, int out_size) {
    const float* x   = (const float*)d_in[0];
    const int*   ei  = (const int*)d_in[1];
    const int*   bat = (const int*)d_in[2];
    const float* W1  = (const float*)d_in[3];
    const float* b1  = (const float*)d_in[4];
    const float* g1  = (const float*)d_in[5];
    const float* bt1 = (const float*)d_in[6];
    const float* W2  = (const float*)d_in[7];
    const float* b2  = (const float*)d_in[8];
    const float* g2  = (const float*)d_in[9];
    const float* bt2 = (const float*)d_in[10];
    const float* Wc1 = (const float*)d_in[11];
    const float* bc1 = (const float*)d_in[12];
    const float* Wc2 = (const float*)d_in[13];
    const float* bc2 = (const float*)d_in[14];
    float* out = (float*)d_out;

    float *pA, *pB, *pC, *pStats;
    cudaGetSymbolAddress((void**)&pA, d_A);
    cudaGetSymbolAddress((void**)&pB, d_B);
    cudaGetSymbolAddress((void**)&pC, d_C);
    cudaGetSymbolAddress((void**)&pStats, d_stats);

    k_detect<<<1, 32>>>(ei);
    k_zero_init<<<384, 256>>>();
    k_hist<<<(NE + 255) / 256, 256>>>(ei);
    k_scan1<<<196, 256>>>();
    k_scan2<<<1, 256>>>();
    k_scan3<<<196, 256>>>();
    k_fill<<<(NE + 255) / 256, 256>>>(ei);

    for (int L = 0; L < NL; L++) {
        const float* h = (L == 0) ? x : pA;
        float* s1 = pStats + (L * 2 + 0) * (2 * DD);
        float* s2 = pStats + (L * 2 + 1) * (2 * DD);
        k_agg<<<NN / 8, 256>>>(h);
        k_gemm<0><<<M_TILES, 256>>>(pB, W1 + L * DD * DD, b1 + L * DD,
                                    nullptr, nullptr, nullptr, s1, pC);
        k_gemm<1><<<M_TILES, 256>>>(pC, W2 + L * DD * DD, b2 + L * DD,
                                    g1 + L * DD, bt1 + L * DD, s1, s2, pB);
        k_epilogue<<<(NN * 32) / 256, 256>>>(pB, bat, g2 + L * DD, bt2 + L * DD, s2, L);
    }
    k_classifier<<<NG, 128>>>(Wc1, bc1, Wc2, bc2, out);
}

// round 3
// speedup vs baseline: 2.1393x; 1.3808x over previous
#include <cuda_runtime.h>
#include <cuda_bf16.h>

#define NN 50000
#define NE 800000
#define DD 128
#define NL 3
#define NG 256
#define NCLS 10
#define M_TILES 391   // ceil(50000/128)

// ---------------- scratch (static device globals; no allocation) ----------------
__device__ float d_A[NN * DD];          // h (layer output)
__device__ float d_B[NN * DD];          // agg (h+sum), then z2
__device__ float d_C[NN * DD];          // z1
__device__ float d_stats[NL * 2 * 2 * DD];   // per (layer, bn#): [sum[128] | sumsq[128]]
__device__ float d_readout[NG * NL * DD];
__device__ unsigned short d_Wt[6 * 2 * DD * DD];  // [mat][hi/lo][n][k] bf16
__device__ int   d_deg[NN];
__device__ int   d_cur[NN];
__device__ int   d_off[NN + 1];
__device__ int   d_csr[NE];
__device__ int   d_bsum[256];
__device__ int   d_is64;

// ---------------- helpers ----------------
__device__ __forceinline__ void red4(float* p, float4 v) {
    asm volatile("red.global.add.v4.f32 [%0], {%1,%2,%3,%4};"
                 :: "l"(p), "f"(v.x), "f"(v.y), "f"(v.z), "f"(v.w) : "memory");
}
__device__ __forceinline__ unsigned smem_u32(const void* p) {
    unsigned r;
    asm("{ .reg .u64 t; cvta.to.shared.u64 t, %1; cvt.u32.u64 %0, t; }" : "=r"(r) : "l"(p));
    return r;
}
__device__ __forceinline__ void cpasync16(unsigned dst, const void* src) {
    asm volatile("cp.async.cg.shared.global [%0], [%1], 16;" :: "r"(dst), "l"(src));
}
__device__ __forceinline__ void mma16816(float* d, const unsigned* a, const unsigned* b) {
    asm volatile("mma.sync.aligned.m16n8k16.row.col.f32.bf16.bf16.f32 "
                 "{%0,%1,%2,%3},{%4,%5,%6,%7},{%8,%9},{%0,%1,%2,%3};"
                 : "+f"(d[0]), "+f"(d[1]), "+f"(d[2]), "+f"(d[3])
                 : "r"(a[0]), "r"(a[1]), "r"(a[2]), "r"(a[3]), "r"(b[0]), "r"(b[1]));
}
__device__ __forceinline__ void ldsm4(unsigned* r, unsigned addr) {
    asm volatile("ldmatrix.sync.aligned.m8n8.x4.shared.b16 {%0,%1,%2,%3},[%4];"
                 : "=r"(r[0]), "=r"(r[1]), "=r"(r[2]), "=r"(r[3]) : "r"(addr));
}
// split (x,y) into bf16 hi word + bf16 lo word (lo = residual)
__device__ __forceinline__ void bsplit2(float x, float y, unsigned& hi, unsigned& lo) {
    __nv_bfloat162 h = __floats2bfloat162_rn(x, y);
    float rx = x - __bfloat162float(h.x);
    float ry = y - __bfloat162float(h.y);
    __nv_bfloat162 l = __floats2bfloat162_rn(rx, ry);
    hi = *(unsigned*)&h;
    lo = *(unsigned*)&l;
}

// ---------------- small kernels ----------------

__global__ void k_detect(const int* __restrict__ ei) {
    if (threadIdx.x == 0 && blockIdx.x == 0) {
        int z = 1;
#pragma unroll
        for (int i = 1; i < 256; i += 2) z &= (ei[i] == 0);
        d_is64 = z;
    }
}

__global__ void k_zero_init() {
    int i = blockIdx.x * 256 + threadIdx.x;
    if (i < NG * NL * DD) d_readout[i] = 0.f;
    if (i < NL * 2 * 2 * DD) d_stats[i] = 0.f;
    if (i < NN) d_deg[i] = 0;
}

// Pack W -> transposed bf16 hi/lo planes: d_Wt[mat][plane][n][k]
__global__ void k_packW(const float* __restrict__ W1, const float* __restrict__ W2) {
    int id = blockIdx.x * 256 + threadIdx.x;   // 384*256 = 98304 = 6*16384
    int mat = id >> 14;
    int r = id & 16383;
    int n = r & 127, k = r >> 7;
    const float* src = (mat < 3) ? (W1 + mat * 16384) : (W2 + (mat - 3) * 16384);
    float v = src[k * DD + n];
    __nv_bfloat16 hb = __float2bfloat16_rn(v);
    float lof = v - __bfloat162float(hb);
    __nv_bfloat16 lb = __float2bfloat16_rn(lof);
    int base = mat * 32768;
    d_Wt[base + n * DD + k] = __bfloat16_as_ushort(hb);
    d_Wt[base + 16384 + n * DD + k] = __bfloat16_as_ushort(lb);
}

__global__ void k_hist(const int* __restrict__ ei) {
    int e = blockIdx.x * 256 + threadIdx.x;
    if (e >= NE) return;
    int dst = d_is64 ? ei[2 * (NE + e)] : ei[NE + e];
    atomicAdd(&d_deg[dst], 1);
}

__global__ void k_scan1() {
    __shared__ int s[256];
    int t = threadIdx.x;
    int i = blockIdx.x * 256 + t;
    int v = (i < NN) ? d_deg[i] : 0;
    s[t] = v;
    __syncthreads();
#pragma unroll
    for (int d = 1; d < 256; d <<= 1) {
        int x = (t >= d) ? s[t - d] : 0;
        __syncthreads();
        s[t] += x;
        __syncthreads();
    }
    if (i < NN) d_off[i + 1] = s[t];
    if (t == 255) d_bsum[blockIdx.x] = s[255];
}

__global__ void k_scan2() {
    __shared__ int s[256];
    int t = threadIdx.x;
    int v = (t < 196) ? d_bsum[t] : 0;
    s[t] = v;
    __syncthreads();
#pragma unroll
    for (int d = 1; d < 256; d <<= 1) {
        int x = (t >= d) ? s[t - d] : 0;
        __syncthreads();
        s[t] += x;
        __syncthreads();
    }
    if (t < 196) d_bsum[t] = s[t] - v;   // exclusive prefix
}

__global__ void k_scan3() {
    int i = blockIdx.x * 256 + threadIdx.x;
    if (i < NN) { d_off[i + 1] += d_bsum[blockIdx.x]; d_cur[i] = 0; }
    if (i == 0) d_off[0] = 0;
}

__global__ void k_fill(const int* __restrict__ ei) {
    int e = blockIdx.x * 256 + threadIdx.x;
    if (e >= NE) return;
    int src, dst;
    if (d_is64) { src = ei[2 * e]; dst = ei[2 * (NE + e)]; }
    else        { src = ei[e];     dst = ei[NE + e]; }
    int p = atomicAdd(&d_cur[dst], 1);
    d_csr[d_off[dst] + p] = src;
}

// One warp per node: agg = h[node] + sum_{src in CSR[node]} h[src]
__global__ void k_agg(const float* __restrict__ h) {
    int w = (blockIdx.x * 256 + threadIdx.x) >> 5;
    if (w >= NN) return;
    int lane = threadIdx.x & 31;
    int beg = d_off[w], end = d_off[w + 1];
    const float4* hv = (const float4*)h;
    float4 a = hv[(long)w * 32 + lane];
    int j = beg;
    for (; j + 4 <= end; j += 4) {
        int s0 = d_csr[j], s1 = d_csr[j + 1], s2 = d_csr[j + 2], s3 = d_csr[j + 3];
        float4 v0 = hv[(long)s0 * 32 + lane];
        float4 v1 = hv[(long)s1 * 32 + lane];
        float4 v2 = hv[(long)s2 * 32 + lane];
        float4 v3 = hv[(long)s3 * 32 + lane];
        a.x += (v0.x + v1.x) + (v2.x + v3.x);
        a.y += (v0.y + v1.y) + (v2.y + v3.y);
        a.z += (v0.z + v1.z) + (v2.z + v3.z);
        a.w += (v0.w + v1.w) + (v2.w + v3.w);
    }
    for (; j < end; j++) {
        int s0 = d_csr[j];
        float4 v = hv[(long)s0 * 32 + lane];
        a.x += v.x; a.y += v.y; a.z += v.z; a.w += v.w;
    }
    ((float4*)d_B)[(long)w * 32 + lane] = a;
}

// ---------------- tensor-core GEMM (bf16-split, fp32-accurate) ----------------
// out[M,128] = f(P) @ W + bias, fused BN column stats.
// MODE 0: f = identity; MODE 1: f = relu(P*scale+shift) from statsIn.
template <int MODE>
__global__ void __launch_bounds__(256, 2)
k_gemm(const float* __restrict__ P, const unsigned short* __restrict__ Wt,
       const float* __restrict__ bias,
       const float* __restrict__ g, const float* __restrict__ bt,
       const float* __restrict__ statsIn, float* __restrict__ statsOut,
       float* __restrict__ out) {
    // smem: A_hi[128][40]b16, A_lo, W_hi[128][40]b16, W_lo  (pitch 80B, conflict-free)
    __shared__ __align__(16) unsigned char sm[40960];
    unsigned sbase = smem_u32(sm);
    const unsigned AHI = 0, ALO = 10240, WHI = 20480;

    int t = threadIdx.x;
    int lane = t & 31, wid = t >> 5;
    int wm = wid & 3, wn = wid >> 2;
    int m0w = wm * 32, n0w = wn * 64;
    int row0 = blockIdx.x * 128;
    int kc = (t & 7) << 2;

    // prologue: W chunk0 cp.async
#pragma unroll
    for (int i = 0; i < 4; i++) {
        int id = t + i * 256;
        int plane = id >> 9, n = (id >> 2) & 127, q = id & 3;
        cpasync16(sbase + WHI + plane * 10240 + n * 80 + q * 16,
                  Wt + plane * 16384 + n * DD + q * 8);
    }
    asm volatile("cp.async.commit_group;");

    // A chunk0 prefetch
    float4 pa[4];
#pragma unroll
    for (int i = 0; i < 4; i++) {
        int row = (t + i * 256) >> 3;
        int gr = row0 + row;
        pa[i] = (gr < NN) ? *(const float4*)(P + (long)gr * DD + kc)
                          : make_float4(0.f, 0.f, 0.f, 0.f);
    }

    // accumulators init with bias
    float acc[2][8][4];
#pragma unroll
    for (int ni = 0; ni < 8; ni++) {
        int c0 = n0w + 8 * ni + 2 * (lane & 3);
        float b0 = bias[c0], b1 = bias[c0 + 1];
#pragma unroll
        for (int mi = 0; mi < 2; mi++) {
            acc[mi][ni][0] = b0; acc[mi][ni][1] = b1;
            acc[mi][ni][2] = b0; acc[mi][ni][3] = b1;
        }
    }

    for (int c = 0; c < 4; c++) {
        int kk = c * 32;
        // BN1 affine for this thread's k-columns
        float4 sc4, sh4;
        if (MODE == 1) {
            int c0 = kk + kc;
            float4 smv = *(const float4*)(statsIn + c0);
            float4 sq = *(const float4*)(statsIn + DD + c0);
            float4 gv = *(const float4*)(g + c0);
            float4 bv = *(const float4*)(bt + c0);
            float mu, var, r;
            mu = smv.x * (1.f / NN); var = sq.x * (1.f / NN) - mu * mu;
            r = rsqrtf(var + 1e-5f); sc4.x = gv.x * r; sh4.x = fmaf(-mu, sc4.x, bv.x);
            mu = smv.y * (1.f / NN); var = sq.y * (1.f / NN) - mu * mu;
            r = rsqrtf(var + 1e-5f); sc4.y = gv.y * r; sh4.y = fmaf(-mu, sc4.y, bv.y);
            mu = smv.z * (1.f / NN); var = sq.z * (1.f / NN) - mu * mu;
            r = rsqrtf(var + 1e-5f); sc4.z = gv.z * r; sh4.z = fmaf(-mu, sc4.z, bv.z);
            mu = smv.w * (1.f / NN); var = sq.w * (1.f / NN) - mu * mu;
            r = rsqrtf(var + 1e-5f); sc4.w = gv.w * r; sh4.w = fmaf(-mu, sc4.w, bv.w);
        }

        // STS A (transform + split hi/lo)
#pragma unroll
        for (int i = 0; i < 4; i++) {
            int row = (t + i * 256) >> 3;
            float4 v = pa[i];
            if (MODE == 1) {
                v.x = fmaxf(fmaf(v.x, sc4.x, sh4.x), 0.f);
                v.y = fmaxf(fmaf(v.y, sc4.y, sh4.y), 0.f);
                v.z = fmaxf(fmaf(v.z, sc4.z, sh4.z), 0.f);
                v.w = fmaxf(fmaf(v.w, sc4.w, sh4.w), 0.f);
            }
            unsigned h01, l01, h23, l23;
            bsplit2(v.x, v.y, h01, l01);
            bsplit2(v.z, v.w, h23, l23);
            unsigned off = (unsigned)(row * 80 + kc * 2);
            *(unsigned*)(sm + off) = h01;
            *(unsigned*)(sm + off + 4) = h23;
            *(unsigned*)(sm + ALO + off) = l01;
            *(unsigned*)(sm + ALO + off + 4) = l23;
        }

        // prefetch next A chunk
        if (c < 3) {
#pragma unroll
            for (int i = 0; i < 4; i++) {
                int row = (t + i * 256) >> 3;
                int gr = row0 + row;
                pa[i] = (gr < NN) ? *(const float4*)(P + (long)gr * DD + kk + 32 + kc)
                                  : make_float4(0.f, 0.f, 0.f, 0.f);
            }
        }

        asm volatile("cp.async.wait_group 0;");
        __syncthreads();

        // compute: 2 k16 steps
#pragma unroll
        for (int ks = 0; ks < 2; ks++) {
            int kb = ks * 16;
            unsigned ah[2][4], al[2][4];
#pragma unroll
            for (int mi = 0; mi < 2; mi++) {
                unsigned ad = sbase + AHI
                    + (unsigned)((m0w + 16 * mi + (lane & 7) + ((lane >> 3) & 1) * 8) * 80
                                 + (kb + (lane >> 4) * 8) * 2);
                ldsm4(ah[mi], ad);
                ldsm4(al[mi], ad + 10240);
            }
#pragma unroll
            for (int q = 0; q < 4; q++) {
                unsigned bd = sbase + WHI
                    + (unsigned)((n0w + 16 * q + ((lane >> 4) & 1) * 8 + (lane & 7)) * 80
                                 + (kb + ((lane >> 3) & 1) * 8) * 2);
                unsigned bh[4], bl[4];
                ldsm4(bh, bd);
                ldsm4(bl, bd + 10240);
#pragma unroll
                for (int mi = 0; mi < 2; mi++) {
#pragma unroll
                    for (int s = 0; s < 2; s++) {
                        int ni = 2 * q + s;
                        mma16816(acc[mi][ni], ah[mi], bh + 2 * s);
                        mma16816(acc[mi][ni], ah[mi], bl + 2 * s);
                        mma16816(acc[mi][ni], al[mi], bh + 2 * s);
                    }
                }
            }
        }
        __syncthreads();

        // issue next W chunk (single buffer; safe after sync)
        if (c < 3) {
#pragma unroll
            for (int i = 0; i < 4; i++) {
                int id = t + i * 256;
                int plane = id >> 9, n = (id >> 2) & 127, q = id & 3;
                cpasync16(sbase + WHI + plane * 10240 + n * 80 + q * 16,
                          Wt + plane * 16384 + n * DD + (kk + 32) + q * 8);
            }
            asm volatile("cp.async.commit_group;");
        }
    }

    // ---- epilogue: store + fused BN column stats ----
    float* Sa = (float*)sm;            // [4][128]
    float* Sq = (float*)(sm + 2048);   // [4][128]
#pragma unroll
    for (int ni = 0; ni < 8; ni++) {
        int c0 = n0w + 8 * ni + 2 * (lane & 3);
        float s0 = 0.f, q0 = 0.f, s1 = 0.f, q1 = 0.f;
#pragma unroll
        for (int mi = 0; mi < 2; mi++) {
            int r0 = row0 + m0w + 16 * mi + (lane >> 2);
            int r1 = r0 + 8;
            float v0 = acc[mi][ni][0], v1 = acc[mi][ni][1];
            float v2 = acc[mi][ni][2], v3 = acc[mi][ni][3];
            if (r0 < NN) {
                *(float2*)(out + (long)r0 * DD + c0) = make_float2(v0, v1);
                s0 += v0; q0 = fmaf(v0, v0, q0);
                s1 += v1; q1 = fmaf(v1, v1, q1);
            }
            if (r1 < NN) {
                *(float2*)(out + (long)r1 * DD + c0) = make_float2(v2, v3);
                s0 += v2; q0 = fmaf(v2, v2, q0);
                s1 += v3; q1 = fmaf(v3, v3, q1);
            }
        }
#pragma unroll
        for (int m = 4; m <= 16; m <<= 1) {
            s0 += __shfl_xor_sync(0xffffffffu, s0, m);
            q0 += __shfl_xor_sync(0xffffffffu, q0, m);
            s1 += __shfl_xor_sync(0xffffffffu, s1, m);
            q1 += __shfl_xor_sync(0xffffffffu, q1, m);
        }
        if (lane < 4) {
            int cc = n0w + 8 * ni + 2 * lane;
            Sa[wm * 128 + cc] = s0; Sa[wm * 128 + cc + 1] = s1;
            Sq[wm * 128 + cc] = q0; Sq[wm * 128 + cc + 1] = q1;
        }
    }
    __syncthreads();
    if (t < 128) {
        float S = Sa[t] + Sa[128 + t] + Sa[256 + t] + Sa[384 + t];
        float Q = Sq[t] + Sq[128 + t] + Sq[256 + t] + Sq[384 + t];
        atomicAdd(&statsOut[t], S);
        atomicAdd(&statsOut[DD + t], Q);
    }
}

// Final BN+ReLU of layer, write h, vector-reduce into readout[batch].
__global__ void k_epilogue(const float* __restrict__ Z, const int* __restrict__ batch,
                           const float* __restrict__ g, const float* __restrict__ bt,
                           const float* __restrict__ statsIn, int layer) {
    __shared__ float esc[DD], esh[DD];
    int t = threadIdx.x;
    if (t < DD) {
        float mu = statsIn[t] * (1.f / NN);
        float var = statsIn[DD + t] * (1.f / NN) - mu * mu;
        float r = rsqrtf(var + 1e-5f);
        float sc = g[t] * r;
        esc[t] = sc;
        esh[t] = fmaf(-mu, sc, bt[t]);
    }
    __syncthreads();
    int i = blockIdx.x * 256 + t;
    int node = i >> 5;
    int c4 = (i & 31) << 2;
    float4 z = *(const float4*)(Z + (long)node * DD + c4);
    z.x = fmaxf(fmaf(z.x, esc[c4 + 0], esh[c4 + 0]), 0.f);
    z.y = fmaxf(fmaf(z.y, esc[c4 + 1], esh[c4 + 1]), 0.f);
    z.z = fmaxf(fmaf(z.z, esc[c4 + 2], esh[c4 + 2]), 0.f);
    z.w = fmaxf(fmaf(z.w, esc[c4 + 3], esh[c4 + 3]), 0.f);
    *(float4*)(d_A + (long)node * DD + c4) = z;
    int b = d_is64 ? batch[2 * node] : batch[node];
    red4(d_readout + b * (NL * DD) + layer * DD + c4, z);
}

__global__ void k_classifier(const float* __restrict__ Wc1, const float* __restrict__ bc1,
                             const float* __restrict__ Wc2, const float* __restrict__ bc2,
                             float* __restrict__ out) {
    int gidx = blockIdx.x;
    int t = threadIdx.x;
    __shared__ float red[NCLS];
    const float* r = d_readout + gidx * (NL * DD);
    float acc = bc1[t];
#pragma unroll 4
    for (int k = 0; k < NL * DD; k++) acc = fmaf(r[k], Wc1[k * DD + t], acc);
    float h = fmaxf(acc, 0.f);
    if (t < NCLS) red[t] = 0.f;
    __syncthreads();
#pragma unroll
    for (int c = 0; c < NCLS; c++) atomicAdd(&red[c], h * Wc2[t * NCLS + c]);
    __syncthreads();
    if (t < NCLS) out[gidx * NCLS + t] = red[t] + bc2[t];
}

// ---------------- launcher ----------------
extern "C" void kernel_launch(void* const* d_in, const int* in_sizes, int n_in,
                              void* d_out, int out_size) {
    const float* x   = (const float*)d_in[0];
    const int*   ei  = (const int*)d_in[1];
    const int*   bat = (const int*)d_in[2];
    const float* W1  = (const float*)d_in[3];
    const float* b1  = (const float*)d_in[4];
    const float* g1  = (const float*)d_in[5];
    const float* bt1 = (const float*)d_in[6];
    const float* W2  = (const float*)d_in[7];
    const float* b2  = (const float*)d_in[8];
    const float* g2  = (const float*)d_in[9];
    const float* bt2 = (const float*)d_in[10];
    const float* Wc1 = (const float*)d_in[11];
    const float* bc1 = (const float*)d_in[12];
    const float* Wc2 = (const float*)d_in[13];
    const float* bc2 = (const float*)d_in[14];
    float* out = (float*)d_out;

    float *pA, *pB, *pC, *pStats;
    unsigned short* pWt;
    cudaGetSymbolAddress((void**)&pA, d_A);
    cudaGetSymbolAddress((void**)&pB, d_B);
    cudaGetSymbolAddress((void**)&pC, d_C);
    cudaGetSymbolAddress((void**)&pStats, d_stats);
    cudaGetSymbolAddress((void**)&pWt, d_Wt);

    k_detect<<<1, 32>>>(ei);
    k_zero_init<<<384, 256>>>();
    k_packW<<<384, 256>>>(W1, W2);
    k_hist<<<(NE + 255) / 256, 256>>>(ei);
    k_scan1<<<196, 256>>>();
    k_scan2<<<1, 256>>>();
    k_scan3<<<196, 256>>>();
    k_fill<<<(NE + 255) / 256, 256>>>(ei);

    for (int L = 0; L < NL; L++) {
        const float* h = (L == 0) ? x : pA;
        float* s1 = pStats + (L * 2 + 0) * (2 * DD);
        float* s2 = pStats + (L * 2 + 1) * (2 * DD);
        k_agg<<<NN / 8, 256>>>(h);
        k_gemm<0><<<M_TILES, 256>>>(pB, pWt + L * 32768, b1 + L * DD,
                                    nullptr, nullptr, nullptr, s1, pC);
        k_gemm<1><<<M_TILES, 256>>>(pC, pWt + (3 + L) * 32768, b2 + L * DD,
                                    g1 + L * DD, bt1 + L * DD, s1, s2, pB);
        k_epilogue<<<(NN * 32) / 256, 256>>>(pB, bat, g2 + L * DD, bt2 + L * DD, s2, L);
    }
    k_classifier<<<NG, 128>>>(Wc1, bc1, Wc2, bc2, out);
}

// round 4
// speedup vs baseline: 2.2140x; 1.0349x over previous
#include <cuda_runtime.h>
#include <cuda_bf16.h>

#define NN 50000
#define NE 800000
#define DD 128
#define NL 3
#define NG 256
#define NCLS 10
#define M_TILES 391   // ceil(50000/128)

// ---------------- scratch (static device globals; no allocation) ----------------
__device__ unsigned short d_Hb[NN * DD];     // h as bf16 (gather format)
__device__ float d_B[NN * DD];               // agg (fp32), then z2
__device__ float d_C[NN * DD];               // z1
__device__ float d_stats[NL * 2 * 2 * DD];   // per (layer, bn#): [sum[128] | sumsq[128]]
__device__ float d_readout[NG * NL * DD];
__device__ unsigned short d_Wt[6 * 2 * DD * DD];  // [mat][hi/lo][n][k] bf16
__device__ int   d_deg[NN];
__device__ int   d_cur[NN];
__device__ int   d_off[NN + 1];
__device__ int   d_csr[NE];
__device__ int   d_bsum[256];
__device__ int   d_is64;

// ---------------- helpers ----------------
__device__ __forceinline__ void red4(float* p, float4 v) {
    asm volatile("red.global.add.v4.f32 [%0], {%1,%2,%3,%4};"
                 :: "l"(p), "f"(v.x), "f"(v.y), "f"(v.z), "f"(v.w) : "memory");
}
__device__ __forceinline__ unsigned smem_u32(const void* p) {
    unsigned r;
    asm("{ .reg .u64 t; cvta.to.shared.u64 t, %1; cvt.u32.u64 %0, t; }" : "=r"(r) : "l"(p));
    return r;
}
__device__ __forceinline__ void cpasync16(unsigned dst, const void* src) {
    asm volatile("cp.async.cg.shared.global [%0], [%1], 16;" :: "r"(dst), "l"(src));
}
__device__ __forceinline__ void mma16816(float* d, const unsigned* a, const unsigned* b) {
    asm volatile("mma.sync.aligned.m16n8k16.row.col.f32.bf16.bf16.f32 "
                 "{%0,%1,%2,%3},{%4,%5,%6,%7},{%8,%9},{%0,%1,%2,%3};"
                 : "+f"(d[0]), "+f"(d[1]), "+f"(d[2]), "+f"(d[3])
                 : "r"(a[0]), "r"(a[1]), "r"(a[2]), "r"(a[3]), "r"(b[0]), "r"(b[1]));
}
__device__ __forceinline__ void ldsm4(unsigned* r, unsigned addr) {
    asm volatile("ldmatrix.sync.aligned.m8n8.x4.shared.b16 {%0,%1,%2,%3},[%4];"
                 : "=r"(r[0]), "=r"(r[1]), "=r"(r[2]), "=r"(r[3]) : "r"(addr));
}
__device__ __forceinline__ void bsplit2(float x, float y, unsigned& hi, unsigned& lo) {
    __nv_bfloat162 h = __floats2bfloat162_rn(x, y);
    float rx = x - __bfloat162float(h.x);
    float ry = y - __bfloat162float(h.y);
    __nv_bfloat162 l = __floats2bfloat162_rn(rx, ry);
    hi = *(unsigned*)&h;
    lo = *(unsigned*)&l;
}
__device__ __forceinline__ float2 bf2f(unsigned u) {
    return __bfloat1622float2(*(__nv_bfloat162*)&u);
}
__device__ __forceinline__ uint2 f4_to_bf4(float4 v) {
    __nv_bfloat162 a = __floats2bfloat162_rn(v.x, v.y);
    __nv_bfloat162 b = __floats2bfloat162_rn(v.z, v.w);
    uint2 o; o.x = *(unsigned*)&a; o.y = *(unsigned*)&b;
    return o;
}

// ---------------- small kernels ----------------

__global__ void k_detect(const int* __restrict__ ei) {
    if (threadIdx.x == 0 && blockIdx.x == 0) {
        int z = 1;
#pragma unroll
        for (int i = 1; i < 256; i += 2) z &= (ei[i] == 0);
        d_is64 = z;
    }
}

__global__ void k_zero_init() {
    int i = blockIdx.x * 256 + threadIdx.x;
    if (i < NG * NL * DD) d_readout[i] = 0.f;
    if (i < NL * 2 * 2 * DD) d_stats[i] = 0.f;
    if (i < NN) d_deg[i] = 0;
}

// x (fp32) -> d_Hb (bf16)
__global__ void k_convx(const float* __restrict__ x) {
    int i = blockIdx.x * 256 + threadIdx.x;   // NN*32 threads
    float4 v = ((const float4*)x)[i];
    ((uint2*)d_Hb)[i] = f4_to_bf4(v);
}

// Pack W -> transposed bf16 hi/lo planes: d_Wt[mat][plane][n][k]
__global__ void k_packW(const float* __restrict__ W1, const float* __restrict__ W2) {
    int id = blockIdx.x * 256 + threadIdx.x;   // 384*256 = 98304 = 6*16384
    int mat = id >> 14;
    int r = id & 16383;
    int n = r & 127, k = r >> 7;
    const float* src = (mat < 3) ? (W1 + mat * 16384) : (W2 + (mat - 3) * 16384);
    float v = src[k * DD + n];
    __nv_bfloat16 hb = __float2bfloat16_rn(v);
    float lof = v - __bfloat162float(hb);
    __nv_bfloat16 lb = __float2bfloat16_rn(lof);
    int base = mat * 32768;
    d_Wt[base + n * DD + k] = __bfloat16_as_ushort(hb);
    d_Wt[base + 16384 + n * DD + k] = __bfloat16_as_ushort(lb);
}

__global__ void k_hist(const int* __restrict__ ei) {
    int e = blockIdx.x * 256 + threadIdx.x;
    if (e >= NE) return;
    int dst = d_is64 ? ei[2 * (NE + e)] : ei[NE + e];
    atomicAdd(&d_deg[dst], 1);
}

__global__ void k_scan1() {
    __shared__ int s[256];
    int t = threadIdx.x;
    int i = blockIdx.x * 256 + t;
    int v = (i < NN) ? d_deg[i] : 0;
    s[t] = v;
    __syncthreads();
#pragma unroll
    for (int d = 1; d < 256; d <<= 1) {
        int x = (t >= d) ? s[t - d] : 0;
        __syncthreads();
        s[t] += x;
        __syncthreads();
    }
    if (i < NN) d_off[i + 1] = s[t];
    if (t == 255) d_bsum[blockIdx.x] = s[255];
}

__global__ void k_scan2() {
    __shared__ int s[256];
    int t = threadIdx.x;
    int v = (t < 196) ? d_bsum[t] : 0;
    s[t] = v;
    __syncthreads();
#pragma unroll
    for (int d = 1; d < 256; d <<= 1) {
        int x = (t >= d) ? s[t - d] : 0;
        __syncthreads();
        s[t] += x;
        __syncthreads();
    }
    if (t < 196) d_bsum[t] = s[t] - v;   // exclusive prefix
}

__global__ void k_scan3() {
    int i = blockIdx.x * 256 + threadIdx.x;
    if (i < NN) { d_off[i + 1] += d_bsum[blockIdx.x]; d_cur[i] = 0; }
    if (i == 0) d_off[0] = 0;
}

__global__ void k_fill(const int* __restrict__ ei) {
    int e = blockIdx.x * 256 + threadIdx.x;
    if (e >= NE) return;
    int src, dst;
    if (d_is64) { src = ei[2 * e]; dst = ei[2 * (NE + e)]; }
    else        { src = ei[e];     dst = ei[NE + e]; }
    int p = atomicAdd(&d_cur[dst], 1);
    d_csr[d_off[dst] + p] = src;
}

// One warp per node: agg = h[node] + sum_{src in CSR[node]} h[src], bf16 gather.
// Lane owns 8 bytes (4 bf16) of the 256B row; accumulate fp32, write fp32.
__global__ void k_agg() {
    int w = (blockIdx.x * 256 + threadIdx.x) >> 5;
    if (w >= NN) return;
    int lane = threadIdx.x & 31;
    int beg = d_off[w], end = d_off[w + 1];
    const uint2* hv = (const uint2*)d_Hb;   // 32 uint2 per node row
    float4 a;
    {
        uint2 v = hv[(long)w * 32 + lane];
        float2 p0 = bf2f(v.x), p1 = bf2f(v.y);
        a = make_float4(p0.x, p0.y, p1.x, p1.y);
    }
    int j = beg;
    for (; j + 4 <= end; j += 4) {
        int s0 = d_csr[j], s1 = d_csr[j + 1], s2 = d_csr[j + 2], s3 = d_csr[j + 3];
        uint2 v0 = hv[(long)s0 * 32 + lane];
        uint2 v1 = hv[(long)s1 * 32 + lane];
        uint2 v2 = hv[(long)s2 * 32 + lane];
        uint2 v3 = hv[(long)s3 * 32 + lane];
        float2 p;
        p = bf2f(v0.x); a.x += p.x; a.y += p.y;
        p = bf2f(v0.y); a.z += p.x; a.w += p.y;
        p = bf2f(v1.x); a.x += p.x; a.y += p.y;
        p = bf2f(v1.y); a.z += p.x; a.w += p.y;
        p = bf2f(v2.x); a.x += p.x; a.y += p.y;
        p = bf2f(v2.y); a.z += p.x; a.w += p.y;
        p = bf2f(v3.x); a.x += p.x; a.y += p.y;
        p = bf2f(v3.y); a.z += p.x; a.w += p.y;
    }
    for (; j < end; j++) {
        int s0 = d_csr[j];
        uint2 v = hv[(long)s0 * 32 + lane];
        float2 p;
        p = bf2f(v.x); a.x += p.x; a.y += p.y;
        p = bf2f(v.y); a.z += p.x; a.w += p.y;
    }
    ((float4*)d_B)[(long)w * 32 + lane] = a;
}

// ---------------- tensor-core GEMM (bf16-split, fp32-accurate) ----------------
// out[M,128] = f(P) @ W + bias, fused BN column stats.
// MODE 0: f = identity; MODE 1: f = relu(P*scale+shift) from statsIn.
template <int MODE>
__global__ void __launch_bounds__(256, 2)
k_gemm(const float* __restrict__ P, const unsigned short* __restrict__ Wt,
       const float* __restrict__ bias,
       const float* __restrict__ g, const float* __restrict__ bt,
       const float* __restrict__ statsIn, float* __restrict__ statsOut,
       float* __restrict__ out) {
    __shared__ __align__(16) unsigned char sm[40960];
    unsigned sbase = smem_u32(sm);
    const unsigned AHI = 0, ALO = 10240, WHI = 20480;

    int t = threadIdx.x;
    int lane = t & 31, wid = t >> 5;
    int wm = wid & 3, wn = wid >> 2;
    int m0w = wm * 32, n0w = wn * 64;
    int row0 = blockIdx.x * 128;
    int kc = (t & 7) << 2;

#pragma unroll
    for (int i = 0; i < 4; i++) {
        int id = t + i * 256;
        int plane = id >> 9, n = (id >> 2) & 127, q = id & 3;
        cpasync16(sbase + WHI + plane * 10240 + n * 80 + q * 16,
                  Wt + plane * 16384 + n * DD + q * 8);
    }
    asm volatile("cp.async.commit_group;");

    float4 pa[4];
#pragma unroll
    for (int i = 0; i < 4; i++) {
        int row = (t + i * 256) >> 3;
        int gr = row0 + row;
        pa[i] = (gr < NN) ? *(const float4*)(P + (long)gr * DD + kc)
                          : make_float4(0.f, 0.f, 0.f, 0.f);
    }

    float acc[2][8][4];
#pragma unroll
    for (int ni = 0; ni < 8; ni++) {
        int c0 = n0w + 8 * ni + 2 * (lane & 3);
        float b0 = bias[c0], b1 = bias[c0 + 1];
#pragma unroll
        for (int mi = 0; mi < 2; mi++) {
            acc[mi][ni][0] = b0; acc[mi][ni][1] = b1;
            acc[mi][ni][2] = b0; acc[mi][ni][3] = b1;
        }
    }

    for (int c = 0; c < 4; c++) {
        int kk = c * 32;
        float4 sc4, sh4;
        if (MODE == 1) {
            int c0 = kk + kc;
            float4 smv = *(const float4*)(statsIn + c0);
            float4 sq = *(const float4*)(statsIn + DD + c0);
            float4 gv = *(const float4*)(g + c0);
            float4 bv = *(const float4*)(bt + c0);
            float mu, var, r;
            mu = smv.x * (1.f / NN); var = sq.x * (1.f / NN) - mu * mu;
            r = rsqrtf(var + 1e-5f); sc4.x = gv.x * r; sh4.x = fmaf(-mu, sc4.x, bv.x);
            mu = smv.y * (1.f / NN); var = sq.y * (1.f / NN) - mu * mu;
            r = rsqrtf(var + 1e-5f); sc4.y = gv.y * r; sh4.y = fmaf(-mu, sc4.y, bv.y);
            mu = smv.z * (1.f / NN); var = sq.z * (1.f / NN) - mu * mu;
            r = rsqrtf(var + 1e-5f); sc4.z = gv.z * r; sh4.z = fmaf(-mu, sc4.z, bv.z);
            mu = smv.w * (1.f / NN); var = sq.w * (1.f / NN) - mu * mu;
            r = rsqrtf(var + 1e-5f); sc4.w = gv.w * r; sh4.w = fmaf(-mu, sc4.w, bv.w);
        }

#pragma unroll
        for (int i = 0; i < 4; i++) {
            int row = (t + i * 256) >> 3;
            float4 v = pa[i];
            if (MODE == 1) {
                v.x = fmaxf(fmaf(v.x, sc4.x, sh4.x), 0.f);
                v.y = fmaxf(fmaf(v.y, sc4.y, sh4.y), 0.f);
                v.z = fmaxf(fmaf(v.z, sc4.z, sh4.z), 0.f);
                v.w = fmaxf(fmaf(v.w, sc4.w, sh4.w), 0.f);
            }
            unsigned h01, l01, h23, l23;
            bsplit2(v.x, v.y, h01, l01);
            bsplit2(v.z, v.w, h23, l23);
            unsigned off = (unsigned)(row * 80 + kc * 2);
            *(unsigned*)(sm + off) = h01;
            *(unsigned*)(sm + off + 4) = h23;
            *(unsigned*)(sm + ALO + off) = l01;
            *(unsigned*)(sm + ALO + off + 4) = l23;
        }

        if (c < 3) {
#pragma unroll
            for (int i = 0; i < 4; i++) {
                int row = (t + i * 256) >> 3;
                int gr = row0 + row;
                pa[i] = (gr < NN) ? *(const float4*)(P + (long)gr * DD + kk + 32 + kc)
                                  : make_float4(0.f, 0.f, 0.f, 0.f);
            }
        }

        asm volatile("cp.async.wait_group 0;");
        __syncthreads();

#pragma unroll
        for (int ks = 0; ks < 2; ks++) {
            int kb = ks * 16;
            unsigned ah[2][4], al[2][4];
#pragma unroll
            for (int mi = 0; mi < 2; mi++) {
                unsigned ad = sbase + AHI
                    + (unsigned)((m0w + 16 * mi + (lane & 7) + ((lane >> 3) & 1) * 8) * 80
                                 + (kb + (lane >> 4) * 8) * 2);
                ldsm4(ah[mi], ad);
                ldsm4(al[mi], ad + 10240);
            }
#pragma unroll
            for (int q = 0; q < 4; q++) {
                unsigned bd = sbase + WHI
                    + (unsigned)((n0w + 16 * q + ((lane >> 4) & 1) * 8 + (lane & 7)) * 80
                                 + (kb + ((lane >> 3) & 1) * 8) * 2);
                unsigned bh[4], bl[4];
                ldsm4(bh, bd);
                ldsm4(bl, bd + 10240);
#pragma unroll
                for (int mi = 0; mi < 2; mi++) {
#pragma unroll
                    for (int s = 0; s < 2; s++) {
                        int ni = 2 * q + s;
                        mma16816(acc[mi][ni], ah[mi], bh + 2 * s);
                        mma16816(acc[mi][ni], ah[mi], bl + 2 * s);
                        mma16816(acc[mi][ni], al[mi], bh + 2 * s);
                    }
                }
            }
        }
        __syncthreads();

        if (c < 3) {
#pragma unroll
            for (int i = 0; i < 4; i++) {
                int id = t + i * 256;
                int plane = id >> 9, n = (id >> 2) & 127, q = id & 3;
                cpasync16(sbase + WHI + plane * 10240 + n * 80 + q * 16,
                          Wt + plane * 16384 + n * DD + (kk + 32) + q * 8);
            }
            asm volatile("cp.async.commit_group;");
        }
    }

    // ---- epilogue: store + fused BN column stats ----
    float* Sa = (float*)sm;            // [4][128]
    float* Sq = (float*)(sm + 2048);   // [4][128]
#pragma unroll
    for (int ni = 0; ni < 8; ni++) {
        int c0 = n0w + 8 * ni + 2 * (lane & 3);
        float s0 = 0.f, q0 = 0.f, s1 = 0.f, q1 = 0.f;
#pragma unroll
        for (int mi = 0; mi < 2; mi++) {
            int r0 = row0 + m0w + 16 * mi + (lane >> 2);
            int r1 = r0 + 8;
            float v0 = acc[mi][ni][0], v1 = acc[mi][ni][1];
            float v2 = acc[mi][ni][2], v3 = acc[mi][ni][3];
            if (r0 < NN) {
                *(float2*)(out + (long)r0 * DD + c0) = make_float2(v0, v1);
                s0 += v0; q0 = fmaf(v0, v0, q0);
                s1 += v1; q1 = fmaf(v1, v1, q1);
            }
            if (r1 < NN) {
                *(float2*)(out + (long)r1 * DD + c0) = make_float2(v2, v3);
                s0 += v2; q0 = fmaf(v2, v2, q0);
                s1 += v3; q1 = fmaf(v3, v3, q1);
            }
        }
#pragma unroll
        for (int m = 4; m <= 16; m <<= 1) {
            s0 += __shfl_xor_sync(0xffffffffu, s0, m);
            q0 += __shfl_xor_sync(0xffffffffu, q0, m);
            s1 += __shfl_xor_sync(0xffffffffu, s1, m);
            q1 += __shfl_xor_sync(0xffffffffu, q1, m);
        }
        if (lane < 4) {
            int cc = n0w + 8 * ni + 2 * lane;
            Sa[wm * 128 + cc] = s0; Sa[wm * 128 + cc + 1] = s1;
            Sq[wm * 128 + cc] = q0; Sq[wm * 128 + cc + 1] = q1;
        }
    }
    __syncthreads();
    if (t < 128) {
        float S = Sa[t] + Sa[128 + t] + Sa[256 + t] + Sa[384 + t];
        float Q = Sq[t] + Sq[128 + t] + Sq[256 + t] + Sq[384 + t];
        atomicAdd(&statsOut[t], S);
        atomicAdd(&statsOut[DD + t], Q);
    }
}

// Final BN+ReLU of layer: write bf16 h, vector-reduce into readout[batch].
__global__ void k_epilogue(const float* __restrict__ Z, const int* __restrict__ batch,
                           const float* __restrict__ g, const float* __restrict__ bt,
                           const float* __restrict__ statsIn, int layer) {
    __shared__ float esc[DD], esh[DD];
    int t = threadIdx.x;
    if (t < DD) {
        float mu = statsIn[t] * (1.f / NN);
        float var = statsIn[DD + t] * (1.f / NN) - mu * mu;
        float r = rsqrtf(var + 1e-5f);
        float sc = g[t] * r;
        esc[t] = sc;
        esh[t] = fmaf(-mu, sc, bt[t]);
    }
    __syncthreads();
    int i = blockIdx.x * 256 + t;
    int node = i >> 5;
    int c4 = (i & 31) << 2;
    float4 z = *(const float4*)(Z + (long)node * DD + c4);
    z.x = fmaxf(fmaf(z.x, esc[c4 + 0], esh[c4 + 0]), 0.f);
    z.y = fmaxf(fmaf(z.y, esc[c4 + 1], esh[c4 + 1]), 0.f);
    z.z = fmaxf(fmaf(z.z, esc[c4 + 2], esh[c4 + 2]), 0.f);
    z.w = fmaxf(fmaf(z.w, esc[c4 + 3], esh[c4 + 3]), 0.f);
    *(uint2*)(d_Hb + (long)node * DD + c4) = f4_to_bf4(z);
    int b = d_is64 ? batch[2 * node] : batch[node];
    red4(d_readout + b * (NL * DD) + layer * DD + c4, z);
}

__global__ void k_classifier(const float* __restrict__ Wc1, const float* __restrict__ bc1,
                             const float* __restrict__ Wc2, const float* __restrict__ bc2,
                             float* __restrict__ out) {
    int gidx = blockIdx.x;
    int t = threadIdx.x;
    __shared__ float red[NCLS];
    const float* r = d_readout + gidx * (NL * DD);
    float acc = bc1[t];
#pragma unroll 4
    for (int k = 0; k < NL * DD; k++) acc = fmaf(r[k], Wc1[k * DD + t], acc);
    float h = fmaxf(acc, 0.f);
    if (t < NCLS) red[t] = 0.f;
    __syncthreads();
#pragma unroll
    for (int c = 0; c < NCLS; c++) atomicAdd(&red[c], h * Wc2[t * NCLS + c]);
    __syncthreads();
    if (t < NCLS) out[gidx * NCLS + t] = red[t] + bc2[t];
}

// ---------------- launcher ----------------
extern "C" void kernel_launch(void* const* d_in, const int* in_sizes, int n_in,
                              void* d_out, int out_size) {
    const float* x   = (const float*)d_in[0];
    const int*   ei  = (const int*)d_in[1];
    const int*   bat = (const int*)d_in[2];
    const float* W1  = (const float*)d_in[3];
    const float* b1  = (const float*)d_in[4];
    const float* g1  = (const float*)d_in[5];
    const float* bt1 = (const float*)d_in[6];
    const float* W2  = (const float*)d_in[7];
    const float* b2  = (const float*)d_in[8];
    const float* g2  = (const float*)d_in[9];
    const float* bt2 = (const float*)d_in[10];
    const float* Wc1 = (const float*)d_in[11];
    const float* bc1 = (const float*)d_in[12];
    const float* Wc2 = (const float*)d_in[13];
    const float* bc2 = (const float*)d_in[14];
    float* out = (float*)d_out;

    float *pB, *pC, *pStats;
    unsigned short* pWt;
    cudaGetSymbolAddress((void**)&pB, d_B);
    cudaGetSymbolAddress((void**)&pC, d_C);
    cudaGetSymbolAddress((void**)&pStats, d_stats);
    cudaGetSymbolAddress((void**)&pWt, d_Wt);

    k_detect<<<1, 32>>>(ei);
    k_zero_init<<<384, 256>>>();
    k_convx<<<(NN * 32) / 256, 256>>>(x);
    k_packW<<<384, 256>>>(W1, W2);
    k_hist<<<(NE + 255) / 256, 256>>>(ei);
    k_scan1<<<196, 256>>>();
    k_scan2<<<1, 256>>>();
    k_scan3<<<196, 256>>>();
    k_fill<<<(NE + 255) / 256, 256>>>(ei);

    for (int L = 0; L < NL; L++) {
        float* s1 = pStats + (L * 2 + 0) * (2 * DD);
        float* s2 = pStats + (L * 2 + 1) * (2 * DD);
        k_agg<<<NN / 8, 256>>>();
        k_gemm<0><<<M_TILES, 256>>>(pB, pWt + L * 32768, b1 + L * DD,
                                    nullptr, nullptr, nullptr, s1, pC);
        k_gemm<1><<<M_TILES, 256>>>(pC, pWt + (3 + L) * 32768, b2 + L * DD,
                                    g1 + L * DD, bt1 + L * DD, s1, s2, pB);
        k_epilogue<<<(NN * 32) / 256, 256>>>(pB, bat, g2 + L * DD, bt2 + L * DD, s2, L);
    }
    k_classifier<<<NG, 128>>>(Wc1, bc1, Wc2, bc2, out);
}